// round 1
// baseline (speedup 1.0000x reference)
#include <cuda_runtime.h>
#include <cstdint>

// Problem shape (fixed by dataset): N=50000 nodes, K=8 relations, D=64.
#define DDIM 64
#define MAX_NODES 50000
#define MAX_RELS 8

// Scratch for hw[n][k][o] = sum_d h[n][d] * W[k][d][o]   (102.4 MB)
__device__ float g_hw[(size_t)MAX_NODES * MAX_RELS * DDIM];

// ---------------------------------------------------------------------------
// 64x64-tile fp32 GEMM:  out[n][o] (+ bias[o]) = sum_d A[n][d] * B[k][d][o]
// grid.x tiles nodes (64/block), grid.y = relation index k.
// If out_param == nullptr, writes to g_hw (row_stride passed accordingly).
// 256 threads, each computes a 4x4 micro-tile. Smem padded to 65 -> conflict-free.
// ---------------------------------------------------------------------------
__global__ __launch_bounds__(256) void rgcn_gemm_kernel(
    const float* __restrict__ A,     // [n_rows][64]
    const float* __restrict__ Ball,  // [gridDim.y][64][64]
    const float* __restrict__ bias,  // [64] or nullptr
    float* __restrict__ out_param,   // nullptr -> g_hw
    int n_rows, int row_stride)
{
    __shared__ float As[64][65];  // As[d][node_in_tile]  (transposed)
    __shared__ float Bs[64][65];  // Bs[d][o]

    float* out = out_param ? out_param : g_hw;
    const float* B = Ball + (size_t)blockIdx.y * DDIM * DDIM;
    const int colbase = blockIdx.y * DDIM;
    const int n0 = blockIdx.x * 64;
    const int tid = threadIdx.x;

    // Cooperative loads: 4096 elements each, coalesced from global.
#pragma unroll
    for (int i = 0; i < 16; ++i) {
        int idx = tid + i * 256;
        int r = idx >> 6;      // node-in-tile (A) / d_in (B)
        int c = idx & 63;      // d (A) / o (B)
        int gr = n0 + r;
        As[c][r] = (gr < n_rows) ? A[(size_t)gr * DDIM + c] : 0.0f;
        Bs[r][c] = B[idx];
    }
    __syncthreads();

    const int ty = tid >> 4;   // 0..15 -> node rows ty*4..ty*4+3
    const int tx = tid & 15;   // 0..15 -> out cols  tx*4..tx*4+3

    float acc[4][4] = {};
#pragma unroll 16
    for (int d = 0; d < 64; ++d) {
        float a0 = As[d][ty * 4 + 0];
        float a1 = As[d][ty * 4 + 1];
        float a2 = As[d][ty * 4 + 2];
        float a3 = As[d][ty * 4 + 3];
        float b0 = Bs[d][tx * 4 + 0];
        float b1 = Bs[d][tx * 4 + 1];
        float b2 = Bs[d][tx * 4 + 2];
        float b3 = Bs[d][tx * 4 + 3];
        acc[0][0] += a0 * b0; acc[0][1] += a0 * b1; acc[0][2] += a0 * b2; acc[0][3] += a0 * b3;
        acc[1][0] += a1 * b0; acc[1][1] += a1 * b1; acc[1][2] += a1 * b2; acc[1][3] += a1 * b3;
        acc[2][0] += a2 * b0; acc[2][1] += a2 * b1; acc[2][2] += a2 * b2; acc[2][3] += a2 * b3;
        acc[3][0] += a3 * b0; acc[3][1] += a3 * b1; acc[3][2] += a3 * b2; acc[3][3] += a3 * b3;
    }

    float bb[4] = {0.f, 0.f, 0.f, 0.f};
    if (bias) {
        bb[0] = bias[tx * 4 + 0];
        bb[1] = bias[tx * 4 + 1];
        bb[2] = bias[tx * 4 + 2];
        bb[3] = bias[tx * 4 + 3];
    }

#pragma unroll
    for (int i = 0; i < 4; ++i) {
        int gr = n0 + ty * 4 + i;
        if (gr < n_rows) {
            float4 v;
            v.x = acc[i][0] + bb[0];
            v.y = acc[i][1] + bb[1];
            v.z = acc[i][2] + bb[2];
            v.w = acc[i][3] + bb[3];
            *(float4*)&out[(size_t)gr * row_stride + colbase + tx * 4] = v;
        }
    }
}

// ---------------------------------------------------------------------------
// Edge scatter: for each edge e, out[dst[e]] += hw[src[e], r[e]] * norm[e]
// 16 threads per edge, each handles one float4 (16 x 16B = 256B row, coalesced
// gather; rows are 256B-aligned). Vector reduction red.global.add.v4.f32.
// ---------------------------------------------------------------------------
__global__ __launch_bounds__(256) void rgcn_edge_kernel(
    const float* __restrict__ norm,
    const int* __restrict__ src,
    const int* __restrict__ dst,
    const int* __restrict__ rel,
    float* __restrict__ out,
    int n_edges, int n_rels)
{
    int t = blockIdx.x * blockDim.x + threadIdx.x;
    int e = t >> 4;
    int lane = t & 15;
    if (e >= n_edges) return;

    int s  = src[e];
    int d_ = dst[e];
    int rr = rel[e];
    float nm = norm[e];

    const float4* row = (const float4*)(g_hw + ((size_t)s * n_rels + rr) * DDIM);
    float4 v = row[lane];
    float mx = v.x * nm, my = v.y * nm, mz = v.z * nm, mw = v.w * nm;

    float* p = out + (size_t)d_ * DDIM + lane * 4;
    asm volatile("red.global.add.v4.f32 [%0], {%1, %2, %3, %4};"
                 :: "l"(p), "f"(mx), "f"(my), "f"(mz), "f"(mw)
                 : "memory");
}

// ---------------------------------------------------------------------------
// In-place ReLU over the output, float4-vectorized.
// ---------------------------------------------------------------------------
__global__ __launch_bounds__(256) void rgcn_relu_kernel(float* __restrict__ out, int n4)
{
    int i = blockIdx.x * blockDim.x + threadIdx.x;
    if (i >= n4) return;
    float4 v = ((float4*)out)[i];
    v.x = fmaxf(v.x, 0.0f);
    v.y = fmaxf(v.y, 0.0f);
    v.z = fmaxf(v.z, 0.0f);
    v.w = fmaxf(v.w, 0.0f);
    ((float4*)out)[i] = v;
}

// ---------------------------------------------------------------------------
// Launch: hw-GEMM -> self-loop GEMM (+bias, initializes out) -> edge scatter
//         -> ReLU.  All plain launches, graph-capturable, no allocation.
// Inputs (metadata order): h, norm, W, loop_weight, h_bias, src, dst, r
// ---------------------------------------------------------------------------
extern "C" void kernel_launch(void* const* d_in, const int* in_sizes, int n_in,
                              void* d_out, int out_size)
{
    const float* h    = (const float*)d_in[0];
    const float* norm = (const float*)d_in[1];
    const float* W    = (const float*)d_in[2];
    const float* lw   = (const float*)d_in[3];
    const float* bias = (const float*)d_in[4];
    const int*   src  = (const int*)d_in[5];
    const int*   dst  = (const int*)d_in[6];
    const int*   rel  = (const int*)d_in[7];
    float* out = (float*)d_out;

    int n_nodes = in_sizes[0] / DDIM;
    int n_edges = in_sizes[5];
    int n_rels  = in_sizes[2] / (DDIM * DDIM);

    // 1) hw[n][k][o] into g_hw
    dim3 g_hw_grid((n_nodes + 63) / 64, n_rels);
    rgcn_gemm_kernel<<<g_hw_grid, 256>>>(h, W, nullptr, nullptr,
                                         n_nodes, n_rels * DDIM);

    // 2) out = h @ loop_weight + bias  (fully initializes d_out)
    dim3 g_loop((n_nodes + 63) / 64, 1);
    rgcn_gemm_kernel<<<g_loop, 256>>>(h, lw, bias, out, n_nodes, DDIM);

    // 3) edge scatter with vector atomics
    long long threads = (long long)n_edges * 16;
    int eblocks = (int)((threads + 255) / 256);
    rgcn_edge_kernel<<<eblocks, 256>>>(norm, src, dst, rel, out,
                                       n_edges, n_rels);

    // 4) ReLU
    int n4 = out_size / 4;
    rgcn_relu_kernel<<<(n4 + 255) / 256, 256>>>(out, n4);
}